// round 1
// baseline (speedup 1.0000x reference)
#include <cuda_runtime.h>

#define BATCH 16
#define HW    4096
#define C     256
#define D     32      // q/k head dim (C/8)
#define DV    128     // v head dim (C/2)
#define M_TOTAL (BATCH * HW)   // 65536

#define TQ 128
#define TK 128
#define PSS 132       // padded stride for P tile (multiple of 4 for float4)

// Scratch (device globals; no allocation allowed)
__device__ float d_f [(size_t)M_TOTAL * D];    // keys    8 MB
__device__ float d_g [(size_t)M_TOTAL * D];    // queries 8 MB
__device__ float d_h [(size_t)M_TOTAL * DV];   // values  32 MB
__device__ float d_ob[(size_t)M_TOTAL * DV];   // attn out 32 MB

// ---------------------------------------------------------------------------
// Kernel 1: fused projections  f = xWf+bf, g = xWg+bg, h = xWh+bh
// Treated as one GEMM: [65536,256] @ [256,192], column ranges route to f/g/h.
// BM=64, BN=64, BK=32; 256 threads, 4x4 micro-tile per thread.
// ---------------------------------------------------------------------------
__global__ __launch_bounds__(256) void proj_kernel(
    const float* __restrict__ x,
    const float* __restrict__ Wf, const float* __restrict__ bf,
    const float* __restrict__ Wg, const float* __restrict__ bg,
    const float* __restrict__ Wh, const float* __restrict__ bh)
{
    __shared__ float Ast[32 * 64];  // [k][m]
    __shared__ float Bs [32 * 64];  // [k][n]

    const int m0 = blockIdx.x * 64;
    const int n0 = blockIdx.y * 64;
    const int tid = threadIdx.x;
    const int ty = tid >> 4, tx = tid & 15;

    float acc[4][4] = {};

    for (int k0 = 0; k0 < C; k0 += 32) {
        __syncthreads();
        // A tile: 64 rows x 32 k, transposed into smem
        for (int idx = tid; idx < 64 * 32; idx += 256) {
            int r = idx >> 5, c = idx & 31;
            Ast[c * 64 + r] = x[(size_t)(m0 + r) * C + k0 + c];
        }
        // B tile: 32 k x 64 cols (routed from Wf/Wg/Wh)
        for (int idx = tid; idx < 32 * 64; idx += 256) {
            int r = idx >> 6, c = idx & 63;
            int j = n0 + c;
            float w;
            if (j < 32)      w = Wf[(k0 + r) * 32  + j];
            else if (j < 64) w = Wg[(k0 + r) * 32  + (j - 32)];
            else             w = Wh[(k0 + r) * 128 + (j - 64)];
            Bs[r * 64 + c] = w;
        }
        __syncthreads();

        #pragma unroll
        for (int kk = 0; kk < 32; kk++) {
            float a[4], b[4];
            *(float4*)a = *(const float4*)&Ast[kk * 64 + ty * 4];
            *(float4*)b = *(const float4*)&Bs [kk * 64 + tx * 4];
            #pragma unroll
            for (int i = 0; i < 4; i++)
                #pragma unroll
                for (int j = 0; j < 4; j++)
                    acc[i][j] = fmaf(a[i], b[j], acc[i][j]);
        }
    }

    const int jb = n0 + tx * 4;   // 4 consecutive cols stay within one region
    #pragma unroll
    for (int i = 0; i < 4; i++) {
        const size_t m = (size_t)(m0 + ty * 4 + i);
        if (jb < 32) {
            #pragma unroll
            for (int j = 0; j < 4; j++)
                d_f[m * D + jb + j] = acc[i][j] + bf[jb + j];
        } else if (jb < 64) {
            #pragma unroll
            for (int j = 0; j < 4; j++)
                d_g[m * D + (jb - 32) + j] = acc[i][j] + bg[jb - 32 + j];
        } else {
            #pragma unroll
            for (int j = 0; j < 4; j++)
                d_h[m * DV + (jb - 64) + j] = acc[i][j] + bh[jb - 64 + j];
        }
    }
}

// ---------------------------------------------------------------------------
// Kernel 2: flash attention.  Q = g, K = f, V = h.  No logit scaling (matches ref).
// Block: (q-tile of 128) x batch. 256 threads as 16x16, 8x8 per thread.
// Online softmax state (m, l) replicated across the 16 threads of a row group
// via intra-warp shuffles (rows split lanes 0-15 / 16-31, xor offsets 1..8).
// ---------------------------------------------------------------------------
__global__ __launch_bounds__(256) void attn_kernel()
{
    extern __shared__ float sm[];
    float* Qt = sm;                     // [D][TQ]      4096 f
    float* Kt = Qt + D * TQ;            // [D][TK]      4096 f
    float* Vs = Kt + D * TK;            // [TK][DV]    16384 f
    float* Ps = Vs + TK * DV;           // [TQ][PSS]   16896 f

    const int b  = blockIdx.y;
    const int q0 = blockIdx.x * TQ;
    const int tid = threadIdx.x;
    const int ty = tid >> 4, tx = tid & 15;

    // Load Q tile, transposed to k-major
    {
        const float* gq = d_g + ((size_t)b * HW + q0) * D;
        for (int idx = tid; idx < TQ * D; idx += 256) {
            int r = idx >> 5, c = idx & 31;
            Qt[c * TQ + r] = gq[idx];
        }
    }

    float m[8], l[8], o[8][8];
    #pragma unroll
    for (int i = 0; i < 8; i++) {
        m[i] = -1e30f; l[i] = 0.f;
        #pragma unroll
        for (int j = 0; j < 8; j++) o[i][j] = 0.f;
    }

    for (int k0 = 0; k0 < HW; k0 += TK) {
        __syncthreads();   // previous iteration's Ps/Vs reads complete
        // K tile transposed, V tile row-major
        {
            const float* gk = d_f + ((size_t)b * HW + k0) * D;
            for (int idx = tid; idx < TK * D; idx += 256) {
                int r = idx >> 5, c = idx & 31;
                Kt[c * TK + r] = gk[idx];
            }
            const float* gv = d_h + ((size_t)b * HW + k0) * DV;
            for (int idx = tid * 4; idx < TK * DV; idx += 1024)
                *(float4*)&Vs[idx] = *(const float4*)&gv[idx];
        }
        __syncthreads();

        // S = Q K^T  (128x128, k=32)
        float s[8][8];
        #pragma unroll
        for (int i = 0; i < 8; i++)
            #pragma unroll
            for (int j = 0; j < 8; j++) s[i][j] = 0.f;

        #pragma unroll 8
        for (int k = 0; k < D; k++) {
            float a[8], bb[8];
            *(float4*)(a)      = *(const float4*)&Qt[k * TQ + ty * 8];
            *(float4*)(a + 4)  = *(const float4*)&Qt[k * TQ + ty * 8 + 4];
            *(float4*)(bb)     = *(const float4*)&Kt[k * TK + tx * 8];
            *(float4*)(bb + 4) = *(const float4*)&Kt[k * TK + tx * 8 + 4];
            #pragma unroll
            for (int i = 0; i < 8; i++)
                #pragma unroll
                for (int j = 0; j < 8; j++)
                    s[i][j] = fmaf(a[i], bb[j], s[i][j]);
        }

        // Online softmax update
        #pragma unroll
        for (int i = 0; i < 8; i++) {
            float rm = s[i][0];
            #pragma unroll
            for (int j = 1; j < 8; j++) rm = fmaxf(rm, s[i][j]);
            #pragma unroll
            for (int off = 1; off < 16; off <<= 1)
                rm = fmaxf(rm, __shfl_xor_sync(0xffffffffu, rm, off));
            const float mn = fmaxf(m[i], rm);
            const float corr = __expf(m[i] - mn);
            m[i] = mn;
            float rs = 0.f;
            #pragma unroll
            for (int j = 0; j < 8; j++) {
                float p = __expf(s[i][j] - mn);
                s[i][j] = p;
                rs += p;
            }
            #pragma unroll
            for (int off = 1; off < 16; off <<= 1)
                rs += __shfl_xor_sync(0xffffffffu, rs, off);
            l[i] = l[i] * corr + rs;
            #pragma unroll
            for (int j = 0; j < 8; j++) o[i][j] *= corr;
        }

        // Stage P to smem for the PV GEMM
        #pragma unroll
        for (int i = 0; i < 8; i++) {
            *(float4*)&Ps[(ty * 8 + i) * PSS + tx * 8] =
                make_float4(s[i][0], s[i][1], s[i][2], s[i][3]);
            *(float4*)&Ps[(ty * 8 + i) * PSS + tx * 8 + 4] =
                make_float4(s[i][4], s[i][5], s[i][6], s[i][7]);
        }
        __syncthreads();

        // O += P @ V  (128x128 @ 128x128)
        #pragma unroll 4
        for (int k = 0; k < TK; k++) {
            float a[8], bb[8];
            #pragma unroll
            for (int i = 0; i < 8; i++) a[i] = Ps[(ty * 8 + i) * PSS + k];
            *(float4*)(bb)     = *(const float4*)&Vs[k * DV + tx * 8];
            *(float4*)(bb + 4) = *(const float4*)&Vs[k * DV + tx * 8 + 4];
            #pragma unroll
            for (int i = 0; i < 8; i++)
                #pragma unroll
                for (int j = 0; j < 8; j++)
                    o[i][j] = fmaf(a[i], bb[j], o[i][j]);
        }
    }

    // Normalize and store
    float* go = d_ob + ((size_t)b * HW + q0) * DV;
    #pragma unroll
    for (int i = 0; i < 8; i++) {
        const float inv = 1.0f / l[i];
        const int row = ty * 8 + i;
        #pragma unroll
        for (int j = 0; j < 8; j++) o[i][j] *= inv;
        *(float4*)&go[(size_t)row * DV + tx * 8] =
            make_float4(o[i][0], o[i][1], o[i][2], o[i][3]);
        *(float4*)&go[(size_t)row * DV + tx * 8 + 4] =
            make_float4(o[i][4], o[i][5], o[i][6], o[i][7]);
    }
}

// ---------------------------------------------------------------------------
// Kernel 3: out = x + o @ Wo + bo   ([65536,128] @ [128,256])
// ---------------------------------------------------------------------------
__global__ __launch_bounds__(256) void outproj_kernel(
    const float* __restrict__ x,
    const float* __restrict__ Wo,
    const float* __restrict__ bo,
    float* __restrict__ out)
{
    __shared__ float Ast[32 * 64];
    __shared__ float Bs [32 * 64];

    const int m0 = blockIdx.x * 64;
    const int n0 = blockIdx.y * 64;
    const int tid = threadIdx.x;
    const int ty = tid >> 4, tx = tid & 15;

    float acc[4][4] = {};

    for (int k0 = 0; k0 < DV; k0 += 32) {
        __syncthreads();
        for (int idx = tid; idx < 64 * 32; idx += 256) {
            int r = idx >> 5, c = idx & 31;
            Ast[c * 64 + r] = d_ob[(size_t)(m0 + r) * DV + k0 + c];
        }
        for (int idx = tid; idx < 32 * 64; idx += 256) {
            int r = idx >> 6, c = idx & 63;
            Bs[r * 64 + c] = Wo[(size_t)(k0 + r) * C + n0 + c];
        }
        __syncthreads();

        #pragma unroll
        for (int kk = 0; kk < 32; kk++) {
            float a[4], b[4];
            *(float4*)a = *(const float4*)&Ast[kk * 64 + ty * 4];
            *(float4*)b = *(const float4*)&Bs [kk * 64 + tx * 4];
            #pragma unroll
            for (int i = 0; i < 4; i++)
                #pragma unroll
                for (int j = 0; j < 4; j++)
                    acc[i][j] = fmaf(a[i], b[j], acc[i][j]);
        }
    }

    const int j = n0 + tx * 4;
    const float4 bv = *(const float4*)&bo[j];
    #pragma unroll
    for (int i = 0; i < 4; i++) {
        const size_t m = (size_t)(m0 + ty * 4 + i);
        const float4 xv = *(const float4*)&x[m * C + j];
        float4 r;
        r.x = xv.x + acc[i][0] + bv.x;
        r.y = xv.y + acc[i][1] + bv.y;
        r.z = xv.z + acc[i][2] + bv.z;
        r.w = xv.w + acc[i][3] + bv.w;
        *(float4*)&out[m * C + j] = r;
    }
}

// ---------------------------------------------------------------------------
extern "C" void kernel_launch(void* const* d_in, const int* in_sizes, int n_in,
                              void* d_out, int out_size)
{
    const float* x  = (const float*)d_in[0];
    const float* Wf = (const float*)d_in[1];
    const float* bf = (const float*)d_in[2];
    const float* Wg = (const float*)d_in[3];
    const float* bg = (const float*)d_in[4];
    const float* Wh = (const float*)d_in[5];
    const float* bh = (const float*)d_in[6];
    const float* Wo = (const float*)d_in[7];
    const float* bo = (const float*)d_in[8];
    float* out = (float*)d_out;

    // 1) projections: [65536,256] @ [256,192]
    proj_kernel<<<dim3(M_TOTAL / 64, 3), 256>>>(x, Wf, bf, Wg, bg, Wh, bh);

    // 2) flash attention
    const size_t smem = (size_t)(D * TQ + D * TK + TK * DV + TQ * PSS) * sizeof(float);
    cudaFuncSetAttribute(attn_kernel,
                         cudaFuncAttributeMaxDynamicSharedMemorySize, (int)smem);
    attn_kernel<<<dim3(HW / TQ, BATCH), 256, smem>>>();

    // 3) output projection + bias + residual
    outproj_kernel<<<dim3(M_TOTAL / 64, C / 64), 256>>>(x, Wo, bo, out);
}

// round 2
// speedup vs baseline: 1.7179x; 1.7179x over previous
#include <cuda_runtime.h>
#include <cstdint>

#define BATCH 16
#define HW    4096
#define C     256
#define D     32
#define DV    128
#define M_TOTAL (BATCH * HW)

#define TQ 128
#define TK 128
#define KSS 36     // K smem stride (32 + 4): conflict-free b-frag loads
#define VSS 132    // V smem stride (128 + 4)
#define PSS 132    // P smem stride

// Scratch (device globals; no allocation allowed)
__device__ float d_f [(size_t)M_TOTAL * D];
__device__ float d_g [(size_t)M_TOTAL * D];
__device__ float d_h [(size_t)M_TOTAL * DV];
__device__ float d_ob[(size_t)M_TOTAL * DV];

__device__ __forceinline__ uint32_t f2tf32(float x) {
    uint32_t r;
    asm("cvt.rna.tf32.f32 %0, %1;" : "=r"(r) : "f"(x));
    return r;
}

__device__ __forceinline__ void mma_tf32(float* c, const uint32_t* a,
                                         uint32_t b0, uint32_t b1) {
    asm volatile(
        "mma.sync.aligned.m16n8k8.row.col.f32.tf32.tf32.f32 "
        "{%0,%1,%2,%3}, {%4,%5,%6,%7}, {%8,%9}, {%0,%1,%2,%3};"
        : "+f"(c[0]), "+f"(c[1]), "+f"(c[2]), "+f"(c[3])
        : "r"(a[0]), "r"(a[1]), "r"(a[2]), "r"(a[3]), "r"(b0), "r"(b1));
}

// ---------------------------------------------------------------------------
// Flash attention with tf32 tensor-core mmas.
// 8 warps; warp w owns q-rows [w*16, w*16+16). S-GEMM uses 3xtf32 (near-fp32
// logits); PV uses single tf32 on P (post-softmax, in [0,1]) and V.
// ---------------------------------------------------------------------------
__global__ __launch_bounds__(256, 1) void attn_kernel() {
    extern __shared__ float sm[];
    float* Ksh = sm;                       // [128][36] tf32 hi
    float* Ksl = Ksh + TK * KSS;           // [128][36] tf32 lo
    float* Vs  = Ksl + TK * KSS;           // [128][132] tf32
    float* Ps  = Vs  + TK * VSS;           // [128][132] tf32
    uint32_t* Kshu = (uint32_t*)Ksh;
    uint32_t* Kslu = (uint32_t*)Ksl;
    uint32_t* Vsu  = (uint32_t*)Vs;
    uint32_t* Psu  = (uint32_t*)Ps;

    const int b   = blockIdx.y;
    const int q0  = blockIdx.x * TQ;
    const int tid = threadIdx.x;
    const int w   = tid >> 5;
    const int lid = tid & 31;
    const int lr  = lid >> 2;   // 0..7
    const int lc  = lid & 3;    // 0..3

    // Q fragments (hi/lo tf32), loaded once. Rows: q0 + w*16 + lr (+8).
    uint32_t qh[4][4], ql[4][4];
    {
        const float* gq = d_g + ((size_t)b * HW + q0 + w * 16) * D;
        #pragma unroll
        for (int ks = 0; ks < 4; ks++) {
            float v0 = gq[lr * D + ks * 8 + lc];
            float v1 = gq[(lr + 8) * D + ks * 8 + lc];
            float v2 = gq[lr * D + ks * 8 + lc + 4];
            float v3 = gq[(lr + 8) * D + ks * 8 + lc + 4];
            qh[ks][0] = f2tf32(v0); ql[ks][0] = f2tf32(v0 - __uint_as_float(qh[ks][0]));
            qh[ks][1] = f2tf32(v1); ql[ks][1] = f2tf32(v1 - __uint_as_float(qh[ks][1]));
            qh[ks][2] = f2tf32(v2); ql[ks][2] = f2tf32(v2 - __uint_as_float(qh[ks][2]));
            qh[ks][3] = f2tf32(v3); ql[ks][3] = f2tf32(v3 - __uint_as_float(qh[ks][3]));
        }
    }

    float o[16][4];
    #pragma unroll
    for (int nt = 0; nt < 16; nt++)
        o[nt][0] = o[nt][1] = o[nt][2] = o[nt][3] = 0.f;
    float mrow[2] = {-1e30f, -1e30f};
    float lrow[2] = {0.f, 0.f};

    const int qr = w * 16 + lr;

    for (int k0 = 0; k0 < HW; k0 += TK) {
        __syncthreads();   // protect Ps/Vs/Ks from previous iteration readers

        // K tile -> smem, hi/lo tf32 split
        for (int i = tid; i < TK * 8; i += 256) {
            int row = i >> 3, sl = i & 7;
            float4 v = *(const float4*)&d_f[((size_t)b * HW + k0 + row) * D + sl * 4];
            int base = row * KSS + sl * 4;
            uint32_t h;
            h = f2tf32(v.x); Kshu[base + 0] = h; Kslu[base + 0] = f2tf32(v.x - __uint_as_float(h));
            h = f2tf32(v.y); Kshu[base + 1] = h; Kslu[base + 1] = f2tf32(v.y - __uint_as_float(h));
            h = f2tf32(v.z); Kshu[base + 2] = h; Kslu[base + 2] = f2tf32(v.z - __uint_as_float(h));
            h = f2tf32(v.w); Kshu[base + 3] = h; Kslu[base + 3] = f2tf32(v.w - __uint_as_float(h));
        }
        // V tile -> smem, tf32
        for (int i = tid; i < TK * 32; i += 256) {
            int row = i >> 5, sl = i & 31;
            float4 v = *(const float4*)&d_h[((size_t)b * HW + k0 + row) * DV + sl * 4];
            int base = row * VSS + sl * 4;
            Vsu[base + 0] = f2tf32(v.x);
            Vsu[base + 1] = f2tf32(v.y);
            Vsu[base + 2] = f2tf32(v.z);
            Vsu[base + 3] = f2tf32(v.w);
        }
        __syncthreads();

        // S = Q K^T (3xtf32: qh*kh + ql*kh + qh*kl)
        float s[16][4];
        #pragma unroll
        for (int nt = 0; nt < 16; nt++) {
            s[nt][0] = s[nt][1] = s[nt][2] = s[nt][3] = 0.f;
            #pragma unroll
            for (int ks = 0; ks < 4; ks++) {
                int bi = (nt * 8 + lr) * KSS + ks * 8 + lc;
                uint32_t bh0 = Kshu[bi], bh1 = Kshu[bi + 4];
                uint32_t bl0 = Kslu[bi], bl1 = Kslu[bi + 4];
                mma_tf32(s[nt], qh[ks], bh0, bh1);
                mma_tf32(s[nt], ql[ks], bh0, bh1);
                mma_tf32(s[nt], qh[ks], bl0, bl1);
            }
        }

        // Online softmax (rows: qr -> regs 0,1 ; qr+8 -> regs 2,3)
        float mx0 = -1e30f, mx1 = -1e30f;
        #pragma unroll
        for (int nt = 0; nt < 16; nt++) {
            mx0 = fmaxf(mx0, fmaxf(s[nt][0], s[nt][1]));
            mx1 = fmaxf(mx1, fmaxf(s[nt][2], s[nt][3]));
        }
        mx0 = fmaxf(mx0, __shfl_xor_sync(0xffffffffu, mx0, 1));
        mx0 = fmaxf(mx0, __shfl_xor_sync(0xffffffffu, mx0, 2));
        mx1 = fmaxf(mx1, __shfl_xor_sync(0xffffffffu, mx1, 1));
        mx1 = fmaxf(mx1, __shfl_xor_sync(0xffffffffu, mx1, 2));

        const float mn0 = fmaxf(mrow[0], mx0);
        const float mn1 = fmaxf(mrow[1], mx1);
        const float corr0 = __expf(mrow[0] - mn0);
        const float corr1 = __expf(mrow[1] - mn1);
        mrow[0] = mn0; mrow[1] = mn1;

        float sum0 = 0.f, sum1 = 0.f;
        #pragma unroll
        for (int nt = 0; nt < 16; nt++) {
            s[nt][0] = __expf(s[nt][0] - mn0);
            s[nt][1] = __expf(s[nt][1] - mn0);
            s[nt][2] = __expf(s[nt][2] - mn1);
            s[nt][3] = __expf(s[nt][3] - mn1);
            sum0 += s[nt][0] + s[nt][1];
            sum1 += s[nt][2] + s[nt][3];
        }
        sum0 += __shfl_xor_sync(0xffffffffu, sum0, 1);
        sum0 += __shfl_xor_sync(0xffffffffu, sum0, 2);
        sum1 += __shfl_xor_sync(0xffffffffu, sum1, 1);
        sum1 += __shfl_xor_sync(0xffffffffu, sum1, 2);
        lrow[0] = lrow[0] * corr0 + sum0;
        lrow[1] = lrow[1] * corr1 + sum1;
        #pragma unroll
        for (int nt = 0; nt < 16; nt++) {
            o[nt][0] *= corr0; o[nt][1] *= corr0;
            o[nt][2] *= corr1; o[nt][3] *= corr1;
        }

        // Stage P to smem as tf32 (own warp's rows only -> __syncwarp suffices)
        #pragma unroll
        for (int nt = 0; nt < 16; nt++) {
            uint2 p0 = make_uint2(f2tf32(s[nt][0]), f2tf32(s[nt][1]));
            uint2 p1 = make_uint2(f2tf32(s[nt][2]), f2tf32(s[nt][3]));
            *(uint2*)&Psu[qr * PSS + nt * 8 + 2 * lc]       = p0;
            *(uint2*)&Psu[(qr + 8) * PSS + nt * 8 + 2 * lc] = p1;
        }
        __syncwarp();

        // O += P @ V
        #pragma unroll
        for (int ks = 0; ks < 16; ks++) {
            uint32_t pa[4];
            pa[0] = Psu[qr * PSS + ks * 8 + lc];
            pa[1] = Psu[(qr + 8) * PSS + ks * 8 + lc];
            pa[2] = Psu[qr * PSS + ks * 8 + lc + 4];
            pa[3] = Psu[(qr + 8) * PSS + ks * 8 + lc + 4];
            #pragma unroll
            for (int nt = 0; nt < 16; nt++) {
                int vi = (ks * 8 + lc) * VSS + nt * 8 + lr;
                mma_tf32(o[nt], pa, Vsu[vi], Vsu[vi + 4 * VSS]);
            }
        }
    }

    // Normalize + store
    const float inv0 = 1.f / lrow[0];
    const float inv1 = 1.f / lrow[1];
    float* go = d_ob + ((size_t)b * HW + q0 + w * 16) * DV;
    #pragma unroll
    for (int nt = 0; nt < 16; nt++) {
        *(float2*)&go[(size_t)lr * DV + nt * 8 + 2 * lc] =
            make_float2(o[nt][0] * inv0, o[nt][1] * inv0);
        *(float2*)&go[(size_t)(lr + 8) * DV + nt * 8 + 2 * lc] =
            make_float2(o[nt][2] * inv1, o[nt][3] * inv1);
    }
}

// ---------------------------------------------------------------------------
// Projections: [65536,256] @ [256,192]. BM=128, BN=64, BK=32, 8x4 micro-tile.
// A smem row-major (broadcast scalar LDS, no transpose conflicts).
// ---------------------------------------------------------------------------
#define AST 36
__global__ __launch_bounds__(256) void proj_kernel(
    const float* __restrict__ x,
    const float* __restrict__ Wf, const float* __restrict__ bf,
    const float* __restrict__ Wg, const float* __restrict__ bg,
    const float* __restrict__ Wh, const float* __restrict__ bh)
{
    __shared__ float Ast[128 * AST];  // [m][k]
    __shared__ float Bs [32 * 68];    // [k][n]

    const int m0 = blockIdx.x * 128;
    const int n0 = blockIdx.y * 64;
    const int tid = threadIdx.x;
    const int ty = tid >> 4, tx = tid & 15;

    float acc[8][4] = {};

    for (int k0 = 0; k0 < C; k0 += 32) {
        __syncthreads();
        for (int i = tid; i < 128 * 8; i += 256) {
            int r = i >> 3, sl = i & 7;
            *(float4*)&Ast[r * AST + sl * 4] =
                *(const float4*)&x[(size_t)(m0 + r) * C + k0 + sl * 4];
        }
        for (int i = tid; i < 32 * 16; i += 256) {
            int r = i >> 4, c4 = i & 15;
            int j = n0 + c4 * 4;
            float4 v;
            if (j < 32)      v = *(const float4*)&Wf[(size_t)(k0 + r) * 32 + j];
            else if (j < 64) v = *(const float4*)&Wg[(size_t)(k0 + r) * 32 + j - 32];
            else             v = *(const float4*)&Wh[(size_t)(k0 + r) * 128 + j - 64];
            *(float4*)&Bs[r * 68 + c4 * 4] = v;
        }
        __syncthreads();

        #pragma unroll
        for (int kk = 0; kk < 32; kk++) {
            float a[8];
            #pragma unroll
            for (int i = 0; i < 8; i++) a[i] = Ast[(ty * 8 + i) * AST + kk];
            float bb[4];
            *(float4*)bb = *(const float4*)&Bs[kk * 68 + tx * 4];
            #pragma unroll
            for (int i = 0; i < 8; i++)
                #pragma unroll
                for (int j = 0; j < 4; j++)
                    acc[i][j] = fmaf(a[i], bb[j], acc[i][j]);
        }
    }

    const int j = n0 + tx * 4;
    #pragma unroll
    for (int i = 0; i < 8; i++) {
        const size_t m = (size_t)(m0 + ty * 8 + i);
        if (j < 32) {
            float4 r = make_float4(acc[i][0] + bf[j], acc[i][1] + bf[j + 1],
                                   acc[i][2] + bf[j + 2], acc[i][3] + bf[j + 3]);
            *(float4*)&d_f[m * D + j] = r;
        } else if (j < 64) {
            int jj = j - 32;
            float4 r = make_float4(acc[i][0] + bg[jj], acc[i][1] + bg[jj + 1],
                                   acc[i][2] + bg[jj + 2], acc[i][3] + bg[jj + 3]);
            *(float4*)&d_g[m * D + jj] = r;
        } else {
            int jj = j - 64;
            float4 r = make_float4(acc[i][0] + bh[jj], acc[i][1] + bh[jj + 1],
                                   acc[i][2] + bh[jj + 2], acc[i][3] + bh[jj + 3]);
            *(float4*)&d_h[m * DV + jj] = r;
        }
    }
}

// ---------------------------------------------------------------------------
// Output projection + residual: out = x + o @ Wo + bo  ([65536,128]@[128,256])
// BM=128, BN=128, BK=32, 8x8 micro-tile.
// ---------------------------------------------------------------------------
__global__ __launch_bounds__(256) void outproj_kernel(
    const float* __restrict__ x,
    const float* __restrict__ Wo,
    const float* __restrict__ bo,
    float* __restrict__ out)
{
    __shared__ float Ast[128 * AST];   // [m][k] 128x32
    __shared__ float Bs [32 * 132];    // [k][n] 32x128

    const int m0 = blockIdx.x * 128;
    const int n0 = blockIdx.y * 128;
    const int tid = threadIdx.x;
    const int ty = tid >> 4, tx = tid & 15;

    float acc[8][8] = {};

    for (int k0 = 0; k0 < DV; k0 += 32) {
        __syncthreads();
        for (int i = tid; i < 128 * 8; i += 256) {
            int r = i >> 3, sl = i & 7;
            *(float4*)&Ast[r * AST + sl * 4] =
                *(const float4*)&d_ob[(size_t)(m0 + r) * DV + k0 + sl * 4];
        }
        for (int i = tid; i < 32 * 32; i += 256) {
            int r = i >> 5, c4 = i & 31;
            *(float4*)&Bs[r * 132 + c4 * 4] =
                *(const float4*)&Wo[(size_t)(k0 + r) * C + n0 + c4 * 4];
        }
        __syncthreads();

        #pragma unroll
        for (int kk = 0; kk < 32; kk++) {
            float a[8];
            #pragma unroll
            for (int i = 0; i < 8; i++) a[i] = Ast[(ty * 8 + i) * AST + kk];
            float bb[8];
            *(float4*)(bb)     = *(const float4*)&Bs[kk * 132 + tx * 8];
            *(float4*)(bb + 4) = *(const float4*)&Bs[kk * 132 + tx * 8 + 4];
            #pragma unroll
            for (int i = 0; i < 8; i++)
                #pragma unroll
                for (int j = 0; j < 8; j++)
                    acc[i][j] = fmaf(a[i], bb[j], acc[i][j]);
        }
    }

    const int j = n0 + tx * 8;
    const float4 bv0 = *(const float4*)&bo[j];
    const float4 bv1 = *(const float4*)&bo[j + 4];
    #pragma unroll
    for (int i = 0; i < 8; i++) {
        const size_t m = (size_t)(m0 + ty * 8 + i);
        const float4 xv0 = *(const float4*)&x[m * C + j];
        const float4 xv1 = *(const float4*)&x[m * C + j + 4];
        float4 r0, r1;
        r0.x = xv0.x + acc[i][0] + bv0.x;
        r0.y = xv0.y + acc[i][1] + bv0.y;
        r0.z = xv0.z + acc[i][2] + bv0.z;
        r0.w = xv0.w + acc[i][3] + bv0.w;
        r1.x = xv1.x + acc[i][4] + bv1.x;
        r1.y = xv1.y + acc[i][5] + bv1.y;
        r1.z = xv1.z + acc[i][6] + bv1.z;
        r1.w = xv1.w + acc[i][7] + bv1.w;
        *(float4*)&out[m * C + j]     = r0;
        *(float4*)&out[m * C + j + 4] = r1;
    }
}

// ---------------------------------------------------------------------------
extern "C" void kernel_launch(void* const* d_in, const int* in_sizes, int n_in,
                              void* d_out, int out_size)
{
    const float* x  = (const float*)d_in[0];
    const float* Wf = (const float*)d_in[1];
    const float* bf = (const float*)d_in[2];
    const float* Wg = (const float*)d_in[3];
    const float* bg = (const float*)d_in[4];
    const float* Wh = (const float*)d_in[5];
    const float* bh = (const float*)d_in[6];
    const float* Wo = (const float*)d_in[7];
    const float* bo = (const float*)d_in[8];
    float* out = (float*)d_out;

    proj_kernel<<<dim3(M_TOTAL / 128, 3), 256>>>(x, Wf, bf, Wg, bg, Wh, bh);

    const size_t smem = (size_t)(2 * TK * KSS + TK * VSS + TQ * PSS) * sizeof(float);
    cudaFuncSetAttribute(attn_kernel,
                         cudaFuncAttributeMaxDynamicSharedMemorySize, (int)smem);
    attn_kernel<<<dim3(HW / TQ, BATCH), 256, smem>>>();

    outproj_kernel<<<dim3(M_TOTAL / 128, C / 128), 256>>>(x, Wo, bo, out);
}

// round 3
// speedup vs baseline: 1.7215x; 1.0021x over previous
#include <cuda_runtime.h>
#include <cstdint>

#define BATCH 16
#define HW    4096
#define C     256
#define D     32
#define DV    128
#define M_TOTAL (BATCH * HW)

#define TQ 128
#define TK 128
#define KSS 36     // K smem stride (32 + 4): conflict-free b-frag loads
#define VSS 132    // V smem stride (128 + 4)
#define PSS 132    // P smem stride

// Scratch (device globals; no allocation allowed)
__device__ float d_f [(size_t)M_TOTAL * D];
__device__ float d_g [(size_t)M_TOTAL * D];
__device__ float d_h [(size_t)M_TOTAL * DV];
__device__ float d_ob[(size_t)M_TOTAL * DV];

__device__ __forceinline__ uint32_t f2tf32(float x) {
    uint32_t r;
    asm("cvt.rna.tf32.f32 %0, %1;" : "=r"(r) : "f"(x));
    return r;
}

__device__ __forceinline__ void mma_tf32(float* c, const uint32_t* a,
                                         uint32_t b0, uint32_t b1) {
    asm volatile(
        "mma.sync.aligned.m16n8k8.row.col.f32.tf32.tf32.f32 "
        "{%0,%1,%2,%3}, {%4,%5,%6,%7}, {%8,%9}, {%0,%1,%2,%3};"
        : "+f"(c[0]), "+f"(c[1]), "+f"(c[2]), "+f"(c[3])
        : "r"(a[0]), "r"(a[1]), "r"(a[2]), "r"(a[3]), "r"(b0), "r"(b1));
}

// ---------------------------------------------------------------------------
// Flash attention with tf32 tensor-core mmas.
// 8 warps; warp w owns q-rows [w*16, w*16+16). S-GEMM uses 3xtf32 (near-fp32
// logits); PV uses single tf32 on P (post-softmax, in [0,1]) and V.
// ---------------------------------------------------------------------------
__global__ __launch_bounds__(256, 1) void attn_kernel() {
    extern __shared__ float sm[];
    float* Ksh = sm;                       // [128][36] tf32 hi
    float* Ksl = Ksh + TK * KSS;           // [128][36] tf32 lo
    float* Vs  = Ksl + TK * KSS;           // [128][132] tf32
    float* Ps  = Vs  + TK * VSS;           // [128][132] tf32
    uint32_t* Kshu = (uint32_t*)Ksh;
    uint32_t* Kslu = (uint32_t*)Ksl;
    uint32_t* Vsu  = (uint32_t*)Vs;
    uint32_t* Psu  = (uint32_t*)Ps;

    const int b   = blockIdx.y;
    const int q0  = blockIdx.x * TQ;
    const int tid = threadIdx.x;
    const int w   = tid >> 5;
    const int lid = tid & 31;
    const int lr  = lid >> 2;   // 0..7
    const int lc  = lid & 3;    // 0..3

    // Q fragments (hi/lo tf32), loaded once. Rows: q0 + w*16 + lr (+8).
    uint32_t qh[4][4], ql[4][4];
    {
        const float* gq = d_g + ((size_t)b * HW + q0 + w * 16) * D;
        #pragma unroll
        for (int ks = 0; ks < 4; ks++) {
            float v0 = gq[lr * D + ks * 8 + lc];
            float v1 = gq[(lr + 8) * D + ks * 8 + lc];
            float v2 = gq[lr * D + ks * 8 + lc + 4];
            float v3 = gq[(lr + 8) * D + ks * 8 + lc + 4];
            qh[ks][0] = f2tf32(v0); ql[ks][0] = f2tf32(v0 - __uint_as_float(qh[ks][0]));
            qh[ks][1] = f2tf32(v1); ql[ks][1] = f2tf32(v1 - __uint_as_float(qh[ks][1]));
            qh[ks][2] = f2tf32(v2); ql[ks][2] = f2tf32(v2 - __uint_as_float(qh[ks][2]));
            qh[ks][3] = f2tf32(v3); ql[ks][3] = f2tf32(v3 - __uint_as_float(qh[ks][3]));
        }
    }

    float o[16][4];
    #pragma unroll
    for (int nt = 0; nt < 16; nt++)
        o[nt][0] = o[nt][1] = o[nt][2] = o[nt][3] = 0.f;
    float mrow[2] = {-1e30f, -1e30f};
    float lrow[2] = {0.f, 0.f};

    const int qr = w * 16 + lr;

    for (int k0 = 0; k0 < HW; k0 += TK) {
        __syncthreads();   // protect Ps/Vs/Ks from previous iteration readers

        // K tile -> smem, hi/lo tf32 split
        for (int i = tid; i < TK * 8; i += 256) {
            int row = i >> 3, sl = i & 7;
            float4 v = *(const float4*)&d_f[((size_t)b * HW + k0 + row) * D + sl * 4];
            int base = row * KSS + sl * 4;
            uint32_t h;
            h = f2tf32(v.x); Kshu[base + 0] = h; Kslu[base + 0] = f2tf32(v.x - __uint_as_float(h));
            h = f2tf32(v.y); Kshu[base + 1] = h; Kslu[base + 1] = f2tf32(v.y - __uint_as_float(h));
            h = f2tf32(v.z); Kshu[base + 2] = h; Kslu[base + 2] = f2tf32(v.z - __uint_as_float(h));
            h = f2tf32(v.w); Kshu[base + 3] = h; Kslu[base + 3] = f2tf32(v.w - __uint_as_float(h));
        }
        // V tile -> smem, tf32
        for (int i = tid; i < TK * 32; i += 256) {
            int row = i >> 5, sl = i & 31;
            float4 v = *(const float4*)&d_h[((size_t)b * HW + k0 + row) * DV + sl * 4];
            int base = row * VSS + sl * 4;
            Vsu[base + 0] = f2tf32(v.x);
            Vsu[base + 1] = f2tf32(v.y);
            Vsu[base + 2] = f2tf32(v.z);
            Vsu[base + 3] = f2tf32(v.w);
        }
        __syncthreads();

        // S = Q K^T (3xtf32: qh*kh + ql*kh + qh*kl)
        float s[16][4];
        #pragma unroll
        for (int nt = 0; nt < 16; nt++) {
            s[nt][0] = s[nt][1] = s[nt][2] = s[nt][3] = 0.f;
            #pragma unroll
            for (int ks = 0; ks < 4; ks++) {
                int bi = (nt * 8 + lr) * KSS + ks * 8 + lc;
                uint32_t bh0 = Kshu[bi], bh1 = Kshu[bi + 4];
                uint32_t bl0 = Kslu[bi], bl1 = Kslu[bi + 4];
                mma_tf32(s[nt], qh[ks], bh0, bh1);
                mma_tf32(s[nt], ql[ks], bh0, bh1);
                mma_tf32(s[nt], qh[ks], bl0, bl1);
            }
        }

        // Online softmax (rows: qr -> regs 0,1 ; qr+8 -> regs 2,3)
        float mx0 = -1e30f, mx1 = -1e30f;
        #pragma unroll
        for (int nt = 0; nt < 16; nt++) {
            mx0 = fmaxf(mx0, fmaxf(s[nt][0], s[nt][1]));
            mx1 = fmaxf(mx1, fmaxf(s[nt][2], s[nt][3]));
        }
        mx0 = fmaxf(mx0, __shfl_xor_sync(0xffffffffu, mx0, 1));
        mx0 = fmaxf(mx0, __shfl_xor_sync(0xffffffffu, mx0, 2));
        mx1 = fmaxf(mx1, __shfl_xor_sync(0xffffffffu, mx1, 1));
        mx1 = fmaxf(mx1, __shfl_xor_sync(0xffffffffu, mx1, 2));

        const float mn0 = fmaxf(mrow[0], mx0);
        const float mn1 = fmaxf(mrow[1], mx1);
        const float corr0 = __expf(mrow[0] - mn0);
        const float corr1 = __expf(mrow[1] - mn1);
        mrow[0] = mn0; mrow[1] = mn1;

        float sum0 = 0.f, sum1 = 0.f;
        #pragma unroll
        for (int nt = 0; nt < 16; nt++) {
            s[nt][0] = __expf(s[nt][0] - mn0);
            s[nt][1] = __expf(s[nt][1] - mn0);
            s[nt][2] = __expf(s[nt][2] - mn1);
            s[nt][3] = __expf(s[nt][3] - mn1);
            sum0 += s[nt][0] + s[nt][1];
            sum1 += s[nt][2] + s[nt][3];
        }
        sum0 += __shfl_xor_sync(0xffffffffu, sum0, 1);
        sum0 += __shfl_xor_sync(0xffffffffu, sum0, 2);
        sum1 += __shfl_xor_sync(0xffffffffu, sum1, 1);
        sum1 += __shfl_xor_sync(0xffffffffu, sum1, 2);
        lrow[0] = lrow[0] * corr0 + sum0;
        lrow[1] = lrow[1] * corr1 + sum1;
        #pragma unroll
        for (int nt = 0; nt < 16; nt++) {
            o[nt][0] *= corr0; o[nt][1] *= corr0;
            o[nt][2] *= corr1; o[nt][3] *= corr1;
        }

        // Stage P to smem as tf32 (own warp's rows only -> __syncwarp suffices)
        #pragma unroll
        for (int nt = 0; nt < 16; nt++) {
            uint2 p0 = make_uint2(f2tf32(s[nt][0]), f2tf32(s[nt][1]));
            uint2 p1 = make_uint2(f2tf32(s[nt][2]), f2tf32(s[nt][3]));
            *(uint2*)&Psu[qr * PSS + nt * 8 + 2 * lc]       = p0;
            *(uint2*)&Psu[(qr + 8) * PSS + nt * 8 + 2 * lc] = p1;
        }
        __syncwarp();

        // O += P @ V
        #pragma unroll
        for (int ks = 0; ks < 16; ks++) {
            uint32_t pa[4];
            pa[0] = Psu[qr * PSS + ks * 8 + lc];
            pa[1] = Psu[(qr + 8) * PSS + ks * 8 + lc];
            pa[2] = Psu[qr * PSS + ks * 8 + lc + 4];
            pa[3] = Psu[(qr + 8) * PSS + ks * 8 + lc + 4];
            #pragma unroll
            for (int nt = 0; nt < 16; nt++) {
                int vi = (ks * 8 + lc) * VSS + nt * 8 + lr;
                mma_tf32(o[nt], pa, Vsu[vi], Vsu[vi + 4 * VSS]);
            }
        }
    }

    // Normalize + store
    const float inv0 = 1.f / lrow[0];
    const float inv1 = 1.f / lrow[1];
    float* go = d_ob + ((size_t)b * HW + q0 + w * 16) * DV;
    #pragma unroll
    for (int nt = 0; nt < 16; nt++) {
        *(float2*)&go[(size_t)lr * DV + nt * 8 + 2 * lc] =
            make_float2(o[nt][0] * inv0, o[nt][1] * inv0);
        *(float2*)&go[(size_t)(lr + 8) * DV + nt * 8 + 2 * lc] =
            make_float2(o[nt][2] * inv1, o[nt][3] * inv1);
    }
}

// ---------------------------------------------------------------------------
// Projections: [65536,256] @ [256,192]. BM=128, BN=64, BK=32, 8x4 micro-tile.
// A smem row-major (broadcast scalar LDS, no transpose conflicts).
// ---------------------------------------------------------------------------
#define AST 36
__global__ __launch_bounds__(256) void proj_kernel(
    const float* __restrict__ x,
    const float* __restrict__ Wf, const float* __restrict__ bf,
    const float* __restrict__ Wg, const float* __restrict__ bg,
    const float* __restrict__ Wh, const float* __restrict__ bh)
{
    __shared__ float Ast[128 * AST];  // [m][k]
    __shared__ float Bs [32 * 68];    // [k][n]

    const int m0 = blockIdx.x * 128;
    const int n0 = blockIdx.y * 64;
    const int tid = threadIdx.x;
    const int ty = tid >> 4, tx = tid & 15;

    float acc[8][4] = {};

    for (int k0 = 0; k0 < C; k0 += 32) {
        __syncthreads();
        for (int i = tid; i < 128 * 8; i += 256) {
            int r = i >> 3, sl = i & 7;
            *(float4*)&Ast[r * AST + sl * 4] =
                *(const float4*)&x[(size_t)(m0 + r) * C + k0 + sl * 4];
        }
        for (int i = tid; i < 32 * 16; i += 256) {
            int r = i >> 4, c4 = i & 15;
            int j = n0 + c4 * 4;
            float4 v;
            if (j < 32)      v = *(const float4*)&Wf[(size_t)(k0 + r) * 32 + j];
            else if (j < 64) v = *(const float4*)&Wg[(size_t)(k0 + r) * 32 + j - 32];
            else             v = *(const float4*)&Wh[(size_t)(k0 + r) * 128 + j - 64];
            *(float4*)&Bs[r * 68 + c4 * 4] = v;
        }
        __syncthreads();

        #pragma unroll
        for (int kk = 0; kk < 32; kk++) {
            float a[8];
            #pragma unroll
            for (int i = 0; i < 8; i++) a[i] = Ast[(ty * 8 + i) * AST + kk];
            float bb[4];
            *(float4*)bb = *(const float4*)&Bs[kk * 68 + tx * 4];
            #pragma unroll
            for (int i = 0; i < 8; i++)
                #pragma unroll
                for (int j = 0; j < 4; j++)
                    acc[i][j] = fmaf(a[i], bb[j], acc[i][j]);
        }
    }

    const int j = n0 + tx * 4;
    #pragma unroll
    for (int i = 0; i < 8; i++) {
        const size_t m = (size_t)(m0 + ty * 8 + i);
        if (j < 32) {
            float4 r = make_float4(acc[i][0] + bf[j], acc[i][1] + bf[j + 1],
                                   acc[i][2] + bf[j + 2], acc[i][3] + bf[j + 3]);
            *(float4*)&d_f[m * D + j] = r;
        } else if (j < 64) {
            int jj = j - 32;
            float4 r = make_float4(acc[i][0] + bg[jj], acc[i][1] + bg[jj + 1],
                                   acc[i][2] + bg[jj + 2], acc[i][3] + bg[jj + 3]);
            *(float4*)&d_g[m * D + jj] = r;
        } else {
            int jj = j - 64;
            float4 r = make_float4(acc[i][0] + bh[jj], acc[i][1] + bh[jj + 1],
                                   acc[i][2] + bh[jj + 2], acc[i][3] + bh[jj + 3]);
            *(float4*)&d_h[m * DV + jj] = r;
        }
    }
}

// ---------------------------------------------------------------------------
// Output projection + residual: out = x + o @ Wo + bo  ([65536,128]@[128,256])
// BM=128, BN=128, BK=32, 8x8 micro-tile.
// ---------------------------------------------------------------------------
__global__ __launch_bounds__(256) void outproj_kernel(
    const float* __restrict__ x,
    const float* __restrict__ Wo,
    const float* __restrict__ bo,
    float* __restrict__ out)
{
    __shared__ float Ast[128 * AST];   // [m][k] 128x32
    __shared__ float Bs [32 * 132];    // [k][n] 32x128

    const int m0 = blockIdx.x * 128;
    const int n0 = blockIdx.y * 128;
    const int tid = threadIdx.x;
    const int ty = tid >> 4, tx = tid & 15;

    float acc[8][8] = {};

    for (int k0 = 0; k0 < DV; k0 += 32) {
        __syncthreads();
        for (int i = tid; i < 128 * 8; i += 256) {
            int r = i >> 3, sl = i & 7;
            *(float4*)&Ast[r * AST + sl * 4] =
                *(const float4*)&d_ob[(size_t)(m0 + r) * DV + k0 + sl * 4];
        }
        for (int i = tid; i < 32 * 32; i += 256) {
            int r = i >> 5, c4 = i & 31;
            *(float4*)&Bs[r * 132 + c4 * 4] =
                *(const float4*)&Wo[(size_t)(k0 + r) * C + n0 + c4 * 4];
        }
        __syncthreads();

        #pragma unroll
        for (int kk = 0; kk < 32; kk++) {
            float a[8];
            #pragma unroll
            for (int i = 0; i < 8; i++) a[i] = Ast[(ty * 8 + i) * AST + kk];
            float bb[8];
            *(float4*)(bb)     = *(const float4*)&Bs[kk * 132 + tx * 8];
            *(float4*)(bb + 4) = *(const float4*)&Bs[kk * 132 + tx * 8 + 4];
            #pragma unroll
            for (int i = 0; i < 8; i++)
                #pragma unroll
                for (int j = 0; j < 8; j++)
                    acc[i][j] = fmaf(a[i], bb[j], acc[i][j]);
        }
    }

    const int j = n0 + tx * 8;
    const float4 bv0 = *(const float4*)&bo[j];
    const float4 bv1 = *(const float4*)&bo[j + 4];
    #pragma unroll
    for (int i = 0; i < 8; i++) {
        const size_t m = (size_t)(m0 + ty * 8 + i);
        const float4 xv0 = *(const float4*)&x[m * C + j];
        const float4 xv1 = *(const float4*)&x[m * C + j + 4];
        float4 r0, r1;
        r0.x = xv0.x + acc[i][0] + bv0.x;
        r0.y = xv0.y + acc[i][1] + bv0.y;
        r0.z = xv0.z + acc[i][2] + bv0.z;
        r0.w = xv0.w + acc[i][3] + bv0.w;
        r1.x = xv1.x + acc[i][4] + bv1.x;
        r1.y = xv1.y + acc[i][5] + bv1.y;
        r1.z = xv1.z + acc[i][6] + bv1.z;
        r1.w = xv1.w + acc[i][7] + bv1.w;
        *(float4*)&out[m * C + j]     = r0;
        *(float4*)&out[m * C + j + 4] = r1;
    }
}

// ---------------------------------------------------------------------------
extern "C" void kernel_launch(void* const* d_in, const int* in_sizes, int n_in,
                              void* d_out, int out_size)
{
    const float* x  = (const float*)d_in[0];
    const float* Wf = (const float*)d_in[1];
    const float* bf = (const float*)d_in[2];
    const float* Wg = (const float*)d_in[3];
    const float* bg = (const float*)d_in[4];
    const float* Wh = (const float*)d_in[5];
    const float* bh = (const float*)d_in[6];
    const float* Wo = (const float*)d_in[7];
    const float* bo = (const float*)d_in[8];
    float* out = (float*)d_out;

    proj_kernel<<<dim3(M_TOTAL / 128, 3), 256>>>(x, Wf, bf, Wg, bg, Wh, bh);

    const size_t smem = (size_t)(2 * TK * KSS + TK * VSS + TQ * PSS) * sizeof(float);
    cudaFuncSetAttribute(attn_kernel,
                         cudaFuncAttributeMaxDynamicSharedMemorySize, (int)smem);
    attn_kernel<<<dim3(HW / TQ, BATCH), 256, smem>>>();

    outproj_kernel<<<dim3(M_TOTAL / 128, C / 128), 256>>>(x, Wo, bo, out);
}

// round 4
// speedup vs baseline: 4.3293x; 2.5149x over previous
#include <cuda_runtime.h>
#include <cuda_fp16.h>
#include <cstdint>

#define BATCH 16
#define HW    4096
#define C     256
#define D     32
#define DV    128
#define M_TOTAL (BATCH * HW)

#define TQ 128
#define TK 128
#define NTILES (HW / TK)
#define LOG2E 1.4426950408889634f

// Scratch (device globals; no allocation allowed)
__device__ __align__(16) __half d_fh[(size_t)M_TOTAL * D];   // K hi fp16
__device__ __align__(16) __half d_fl[(size_t)M_TOTAL * D];   // K lo fp16
__device__ float  d_g [(size_t)M_TOTAL * D];                 // Q fp32
__device__ __align__(16) __half d_ht[(size_t)BATCH * DV * HW]; // V fp16, [b][dv][hw]
__device__ float  d_ob[(size_t)M_TOTAL * DV];                // attn out fp32

// pack two f32 -> f16x2 register (lo = first arg)
__device__ __forceinline__ uint32_t packh2(float lo, float hi) {
    uint32_t r;
    asm("cvt.rn.f16x2.f32 %0, %1, %2;" : "=r"(r) : "f"(hi), "f"(lo));
    return r;
}

__device__ __forceinline__ void mma16816(float* c, const uint32_t* a,
                                         uint32_t b0, uint32_t b1) {
    asm volatile(
        "mma.sync.aligned.m16n8k16.row.col.f32.f16.f16.f32 "
        "{%0,%1,%2,%3}, {%4,%5,%6,%7}, {%8,%9}, {%0,%1,%2,%3};"
        : "+f"(c[0]), "+f"(c[1]), "+f"(c[2]), "+f"(c[3])
        : "r"(a[0]), "r"(a[1]), "r"(a[2]), "r"(a[3]), "r"(b0), "r"(b1));
}

__device__ __forceinline__ void cp16(uint32_t sdst, const void* gsrc) {
    asm volatile("cp.async.cg.shared.global [%0], [%1], 16;"
                 :: "r"(sdst), "l"(gsrc));
}

// ---------------------------------------------------------------------------
// Flash attention, fp16 tensor cores, register-resident P, cp.async pipeline.
// 8 warps; warp w owns q-rows [w*16, w*16+16).
// smem per buffer: Kh[128][20u32] @0, Kl @10240, Vt[128 dv][68u32] @20480.
// ---------------------------------------------------------------------------
#define KROW 20              // K smem row stride in u32 (16 data + 4 pad)
#define VROW 68              // Vt smem row stride in u32 (64 data + 4 pad)
#define BUFB 55296           // bytes per buffer

__global__ __launch_bounds__(256, 1) void attn_kernel() {
    extern __shared__ char sm[];
    const uint32_t smem_u32 = (uint32_t)__cvta_generic_to_shared(sm);

    const int b   = blockIdx.y;
    const int q0  = blockIdx.x * TQ;
    const int tid = threadIdx.x;
    const int w   = tid >> 5;
    const int lid = tid & 31;
    const int lr  = lid >> 2;    // 0..7
    const int lc  = lid & 3;     // 0..3

    // ---- Q fragments (fp16 hi/lo, pre-scaled by log2e), loaded once ----
    uint32_t qh[2][4], ql[2][4];
    {
        const float* gq = d_g + ((size_t)b * HW + q0 + w * 16) * D;
        #pragma unroll
        for (int ks = 0; ks < 2; ks++) {
            #pragma unroll
            for (int r = 0; r < 4; r++) {
                const int row = (r & 1) ? (lr + 8) : lr;
                const int col = ks * 16 + ((r & 2) ? 8 : 0) + 2 * lc;
                const float v0 = gq[row * D + col]     * LOG2E;
                const float v1 = gq[row * D + col + 1] * LOG2E;
                uint32_t h = packh2(v0, v1);
                __half2 hh = *reinterpret_cast<__half2*>(&h);
                float2 hf = __half22float2(hh);
                qh[ks][r] = h;
                ql[ks][r] = packh2(v0 - hf.x, v1 - hf.y);
            }
        }
    }

    float o[16][4];
    #pragma unroll
    for (int nt = 0; nt < 16; nt++)
        o[nt][0] = o[nt][1] = o[nt][2] = o[nt][3] = 0.f;
    float lsum[4] = {0.f, 0.f, 0.f, 0.f};
    float mrow0 = -1e30f, mrow1 = -1e30f;

    // ---- async tile loader ----
    auto issue_tile = [&](int t) {
        const uint32_t sb = smem_u32 + (t & 1) * BUFB;
        const int k0 = t * TK;
        #pragma unroll
        for (int i = 0; i < 4; i++) {            // K hi+lo: 1024 chunks
            const int idx = tid + 256 * i;
            const int arr = idx >> 9;
            const int row = (idx >> 2) & 127;
            const int c   = idx & 3;
            const __half* g = (arr ? d_fl : d_fh)
                              + ((size_t)(b * HW + k0 + row)) * D + c * 8;
            cp16(sb + arr * 10240 + row * 80 + c * 16, g);
        }
        #pragma unroll
        for (int i = 0; i < 8; i++) {            // Vt: 2048 chunks
            const int idx = tid + 256 * i;
            const int row = idx >> 4;            // dv
            const int c   = idx & 15;
            const __half* g = d_ht + ((size_t)(b * DV + row)) * HW + k0 + c * 8;
            cp16(sb + 20480 + row * 272 + c * 16, g);
        }
        asm volatile("cp.async.commit_group;");
    };

    issue_tile(0);

    #pragma unroll 1
    for (int t = 0; t < NTILES; t++) {
        if (t + 1 < NTILES) {
            issue_tile(t + 1);
            asm volatile("cp.async.wait_group 1;");
        } else {
            asm volatile("cp.async.wait_group 0;");
        }
        __syncthreads();

        const char* sbuf = sm + (t & 1) * BUFB;
        const uint32_t* Khu = (const uint32_t*)(sbuf);
        const uint32_t* Klu = (const uint32_t*)(sbuf + 10240);
        const uint32_t* Vtu = (const uint32_t*)(sbuf + 20480);

        // ---- S = (Q*log2e) K^T : 2-term fp16 split (qh*kh + ql*kh + qh*kl)
        float s[16][4];
        #pragma unroll
        for (int nt = 0; nt < 16; nt++) {
            s[nt][0] = s[nt][1] = s[nt][2] = s[nt][3] = 0.f;
            #pragma unroll
            for (int ks = 0; ks < 2; ks++) {
                const int bi = (nt * 8 + lr) * KROW + ks * 8 + lc;
                const uint32_t bh0 = Khu[bi], bh1 = Khu[bi + 4];
                const uint32_t bl0 = Klu[bi], bl1 = Klu[bi + 4];
                mma16816(s[nt], qh[ks], bh0, bh1);
                mma16816(s[nt], ql[ks], bh0, bh1);
                mma16816(s[nt], qh[ks], bl0, bl1);
            }
        }

        // ---- online softmax (log2 domain) ----
        float mx0 = fmaxf(s[0][0], s[0][1]);
        float mx1 = fmaxf(s[0][2], s[0][3]);
        #pragma unroll
        for (int nt = 1; nt < 16; nt++) {
            mx0 = fmaxf(mx0, fmaxf(s[nt][0], s[nt][1]));
            mx1 = fmaxf(mx1, fmaxf(s[nt][2], s[nt][3]));
        }
        mx0 = fmaxf(mx0, __shfl_xor_sync(0xffffffffu, mx0, 1));
        mx0 = fmaxf(mx0, __shfl_xor_sync(0xffffffffu, mx0, 2));
        mx1 = fmaxf(mx1, __shfl_xor_sync(0xffffffffu, mx1, 1));
        mx1 = fmaxf(mx1, __shfl_xor_sync(0xffffffffu, mx1, 2));

        const float mn0 = fmaxf(mrow0, mx0);
        const float mn1 = fmaxf(mrow1, mx1);
        const float corr0 = exp2f(mrow0 - mn0);
        const float corr1 = exp2f(mrow1 - mn1);
        mrow0 = mn0; mrow1 = mn1;

        // p = exp2(s - mn), packed straight into PV A-fragments (no smem!)
        uint32_t pa[8][4];
        #pragma unroll
        for (int nt = 0; nt < 16; nt++) {
            const float p0 = exp2f(s[nt][0] - mn0);
            const float p1 = exp2f(s[nt][1] - mn0);
            const float p2 = exp2f(s[nt][2] - mn1);
            const float p3 = exp2f(s[nt][3] - mn1);
            pa[nt >> 1][(nt & 1) ? 2 : 0] = packh2(p0, p1);
            pa[nt >> 1][(nt & 1) ? 3 : 1] = packh2(p2, p3);
        }

        lsum[0] *= corr0; lsum[2] *= corr1;
        #pragma unroll
        for (int nt = 0; nt < 16; nt++) {
            o[nt][0] *= corr0; o[nt][1] *= corr0;
            o[nt][2] *= corr1; o[nt][3] *= corr1;
        }

        // ---- O += P V ;  row-sum via ones-column mma ----
        const uint32_t ONES = 0x3C003C00u;
        #pragma unroll
        for (int ks = 0; ks < 8; ks++) {
            mma16816(lsum, pa[ks], ONES, ONES);
            #pragma unroll
            for (int nt = 0; nt < 16; nt++) {
                const int vi = (nt * 8 + lr) * VROW + ks * 8 + lc;
                mma16816(o[nt], pa[ks], Vtu[vi], Vtu[vi + 4]);
            }
        }
        __syncthreads();
    }

    // ---- normalize + store fp32 ----
    const float inv0 = 1.f / lsum[0];
    const float inv1 = 1.f / lsum[2];
    float* go = d_ob + ((size_t)b * HW + q0 + w * 16) * DV;
    #pragma unroll
    for (int nt = 0; nt < 16; nt++) {
        *(float2*)&go[(size_t)lr * DV + nt * 8 + 2 * lc] =
            make_float2(o[nt][0] * inv0, o[nt][1] * inv0);
        *(float2*)&go[(size_t)(lr + 8) * DV + nt * 8 + 2 * lc] =
            make_float2(o[nt][2] * inv1, o[nt][3] * inv1);
    }
}

// ---------------------------------------------------------------------------
// Projections: [65536,256] @ [256,192]. f -> fp16 hi/lo, g -> f32,
// h -> fp16 transposed [b][dv][hw].
// ---------------------------------------------------------------------------
#define AST 36
__global__ __launch_bounds__(256) void proj_kernel(
    const float* __restrict__ x,
    const float* __restrict__ Wf, const float* __restrict__ bf,
    const float* __restrict__ Wg, const float* __restrict__ bg,
    const float* __restrict__ Wh, const float* __restrict__ bh)
{
    __shared__ float Ast[128 * AST];
    __shared__ float Bs [32 * 68];

    const int m0 = blockIdx.x * 128;
    const int n0 = blockIdx.y * 64;
    const int tid = threadIdx.x;
    const int ty = tid >> 4, tx = tid & 15;

    float acc[8][4] = {};

    for (int k0 = 0; k0 < C; k0 += 32) {
        __syncthreads();
        for (int i = tid; i < 128 * 8; i += 256) {
            int r = i >> 3, sl = i & 7;
            *(float4*)&Ast[r * AST + sl * 4] =
                *(const float4*)&x[(size_t)(m0 + r) * C + k0 + sl * 4];
        }
        for (int i = tid; i < 32 * 16; i += 256) {
            int r = i >> 4, c4 = i & 15;
            int j = n0 + c4 * 4;
            float4 v;
            if (j < 32)      v = *(const float4*)&Wf[(size_t)(k0 + r) * 32 + j];
            else if (j < 64) v = *(const float4*)&Wg[(size_t)(k0 + r) * 32 + j - 32];
            else             v = *(const float4*)&Wh[(size_t)(k0 + r) * 128 + j - 64];
            *(float4*)&Bs[r * 68 + c4 * 4] = v;
        }
        __syncthreads();

        #pragma unroll
        for (int kk = 0; kk < 32; kk++) {
            float a[8];
            #pragma unroll
            for (int i = 0; i < 8; i++) a[i] = Ast[(ty * 8 + i) * AST + kk];
            float bb[4];
            *(float4*)bb = *(const float4*)&Bs[kk * 68 + tx * 4];
            #pragma unroll
            for (int i = 0; i < 8; i++)
                #pragma unroll
                for (int j = 0; j < 4; j++)
                    acc[i][j] = fmaf(a[i], bb[j], acc[i][j]);
        }
    }

    const int j = n0 + tx * 4;
    if (j < 32) {
        // keys: fp16 hi/lo
        uint32_t* ph = (uint32_t*)d_fh;
        uint32_t* pl = (uint32_t*)d_fl;
        #pragma unroll
        for (int i = 0; i < 8; i++) {
            const size_t m = (size_t)(m0 + ty * 8 + i);
            float v0 = acc[i][0] + bf[j],     v1 = acc[i][1] + bf[j + 1];
            float v2 = acc[i][2] + bf[j + 2], v3 = acc[i][3] + bf[j + 3];
            uint32_t h01 = packh2(v0, v1), h23 = packh2(v2, v3);
            __half2 a01 = *reinterpret_cast<__half2*>(&h01);
            __half2 a23 = *reinterpret_cast<__half2*>(&h23);
            float2 f01 = __half22float2(a01), f23 = __half22float2(a23);
            ph[m * 16 + j / 2]     = h01;
            ph[m * 16 + j / 2 + 1] = h23;
            pl[m * 16 + j / 2]     = packh2(v0 - f01.x, v1 - f01.y);
            pl[m * 16 + j / 2 + 1] = packh2(v2 - f23.x, v3 - f23.y);
        }
    } else if (j < 64) {
        const int jj = j - 32;
        #pragma unroll
        for (int i = 0; i < 8; i++) {
            const size_t m = (size_t)(m0 + ty * 8 + i);
            float4 r = make_float4(acc[i][0] + bg[jj], acc[i][1] + bg[jj + 1],
                                   acc[i][2] + bg[jj + 2], acc[i][3] + bg[jj + 3]);
            *(float4*)&d_g[m * D + jj] = r;
        }
    } else {
        // values: fp16, transposed [b][dv][hw]
        const int jj = j - 64;
        const int bb_ = m0 / HW;
        const int mm0 = (m0 % HW) + ty * 8;
        #pragma unroll
        for (int q = 0; q < 4; q++) {
            const int dv = jj + q;
            const float bias = bh[dv];
            uint32_t* dst = (uint32_t*)(d_ht + ((size_t)(bb_ * DV + dv)) * HW + mm0);
            #pragma unroll
            for (int i2 = 0; i2 < 4; i2++) {
                dst[i2] = packh2(acc[2 * i2][q] + bias, acc[2 * i2 + 1][q] + bias);
            }
        }
    }
}

// ---------------------------------------------------------------------------
// Output projection + residual: out = x + o @ Wo + bo
// ---------------------------------------------------------------------------
__global__ __launch_bounds__(256) void outproj_kernel(
    const float* __restrict__ x,
    const float* __restrict__ Wo,
    const float* __restrict__ bo,
    float* __restrict__ out)
{
    __shared__ float Ast[128 * AST];
    __shared__ float Bs [32 * 132];

    const int m0 = blockIdx.x * 128;
    const int n0 = blockIdx.y * 128;
    const int tid = threadIdx.x;
    const int ty = tid >> 4, tx = tid & 15;

    float acc[8][8] = {};

    for (int k0 = 0; k0 < DV; k0 += 32) {
        __syncthreads();
        for (int i = tid; i < 128 * 8; i += 256) {
            int r = i >> 3, sl = i & 7;
            *(float4*)&Ast[r * AST + sl * 4] =
                *(const float4*)&d_ob[(size_t)(m0 + r) * DV + k0 + sl * 4];
        }
        for (int i = tid; i < 32 * 32; i += 256) {
            int r = i >> 5, c4 = i & 31;
            *(float4*)&Bs[r * 132 + c4 * 4] =
                *(const float4*)&Wo[(size_t)(k0 + r) * C + n0 + c4 * 4];
        }
        __syncthreads();

        #pragma unroll
        for (int kk = 0; kk < 32; kk++) {
            float a[8];
            #pragma unroll
            for (int i = 0; i < 8; i++) a[i] = Ast[(ty * 8 + i) * AST + kk];
            float bb[8];
            *(float4*)(bb)     = *(const float4*)&Bs[kk * 132 + tx * 8];
            *(float4*)(bb + 4) = *(const float4*)&Bs[kk * 132 + tx * 8 + 4];
            #pragma unroll
            for (int i = 0; i < 8; i++)
                #pragma unroll
                for (int j = 0; j < 8; j++)
                    acc[i][j] = fmaf(a[i], bb[j], acc[i][j]);
        }
    }

    const int j = n0 + tx * 8;
    const float4 bv0 = *(const float4*)&bo[j];
    const float4 bv1 = *(const float4*)&bo[j + 4];
    #pragma unroll
    for (int i = 0; i < 8; i++) {
        const size_t m = (size_t)(m0 + ty * 8 + i);
        const float4 xv0 = *(const float4*)&x[m * C + j];
        const float4 xv1 = *(const float4*)&x[m * C + j + 4];
        float4 r0, r1;
        r0.x = xv0.x + acc[i][0] + bv0.x;
        r0.y = xv0.y + acc[i][1] + bv0.y;
        r0.z = xv0.z + acc[i][2] + bv0.z;
        r0.w = xv0.w + acc[i][3] + bv0.w;
        r1.x = xv1.x + acc[i][4] + bv1.x;
        r1.y = xv1.y + acc[i][5] + bv1.y;
        r1.z = xv1.z + acc[i][6] + bv1.z;
        r1.w = xv1.w + acc[i][7] + bv1.w;
        *(float4*)&out[m * C + j]     = r0;
        *(float4*)&out[m * C + j + 4] = r1;
    }
}

// ---------------------------------------------------------------------------
extern "C" void kernel_launch(void* const* d_in, const int* in_sizes, int n_in,
                              void* d_out, int out_size)
{
    const float* x  = (const float*)d_in[0];
    const float* Wf = (const float*)d_in[1];
    const float* bf = (const float*)d_in[2];
    const float* Wg = (const float*)d_in[3];
    const float* bg = (const float*)d_in[4];
    const float* Wh = (const float*)d_in[5];
    const float* bh = (const float*)d_in[6];
    const float* Wo = (const float*)d_in[7];
    const float* bo = (const float*)d_in[8];
    float* out = (float*)d_out;

    proj_kernel<<<dim3(M_TOTAL / 128, 3), 256>>>(x, Wf, bf, Wg, bg, Wh, bh);

    const int smem = 2 * BUFB;   // 110592 B
    cudaFuncSetAttribute(attn_kernel,
                         cudaFuncAttributeMaxDynamicSharedMemorySize, smem);
    attn_kernel<<<dim3(HW / TQ, BATCH), 256, smem>>>();

    outproj_kernel<<<dim3(M_TOTAL / 128, C / 128), 256>>>(x, Wo, bo, out);
}